// round 12
// baseline (speedup 1.0000x reference)
#include <cuda_runtime.h>
#include <cuda_fp16.h>
#include <cstddef>

#define NNODES 100000
#define NEDGES 1600000
#define NFEAT  7
#define HID    128
#define NGRAPH 8
#define NCLASS 5

// ---------------------------------------------------------------------------
// Device-global scratch (allocation-free contract)
// ---------------------------------------------------------------------------
__device__ int    g_rowptr[NNODES + 1];
__device__ int    g_cur[NNODES];
__device__ int2   g_epack[NEDGES];        // CSR slot: {src, attr bits}
__device__ float  g_agg7[NNODES * NFEAT];
__device__ float  g_ha[NNODES * HID];
__device__ float  g_hb[NNODES * HID];
__device__ __half g_h16a[NNODES * HID];   // fp16 mirror, ping
__device__ __half g_h16b[NNODES * HID];   // fp16 mirror, pong (race-free fusion)
__device__ float  g_pool[NGRAPH * HID];
__device__ float  g_cnt[NGRAPH];

// ---------------------------------------------------------------------------
// CSR build: histogram -> scan -> fill
// ---------------------------------------------------------------------------
__global__ void hist_kernel(const int* __restrict__ ei) {
    int e = blockIdx.x * blockDim.x + threadIdx.x;
    if (e < NEDGES) atomicAdd(&g_cur[ei[NEDGES + e]], 1);
}

__global__ void scan_kernel() {
    __shared__ int warp_sums[32];
    __shared__ int s_carry;
    int tid = threadIdx.x;
    int lane = tid & 31, wid = tid >> 5;
    if (tid == 0) s_carry = 0;
    __syncthreads();
    for (int base = 0; base < NNODES; base += 1024) {
        int i = base + tid;
        int v = (i < NNODES) ? g_cur[i] : 0;
        int incl = v;
#pragma unroll
        for (int o = 1; o < 32; o <<= 1) {
            int t = __shfl_up_sync(0xffffffffu, incl, o);
            if (lane >= o) incl += t;
        }
        if (lane == 31) warp_sums[wid] = incl;
        __syncthreads();
        if (wid == 0) {
            int ws = warp_sums[lane];
            int wincl = ws;
#pragma unroll
            for (int o = 1; o < 32; o <<= 1) {
                int t = __shfl_up_sync(0xffffffffu, wincl, o);
                if (lane >= o) wincl += t;
            }
            warp_sums[lane] = wincl - ws;
        }
        __syncthreads();
        int excl = incl - v + warp_sums[wid] + s_carry;
        if (i < NNODES) { g_rowptr[i] = excl; g_cur[i] = excl; }
        __syncthreads();
        if (tid == 1023) s_carry = excl + v;
        __syncthreads();
    }
    if (tid == 0) g_rowptr[NNODES] = NEDGES;
}

__global__ void fill_kernel(const int* __restrict__ ei, const float* __restrict__ ea) {
    int e = blockIdx.x * blockDim.x + threadIdx.x;
    if (e >= NEDGES) return;
    int d = ei[NEDGES + e];
    int pos = atomicAdd(&g_cur[d], 1);
    g_epack[pos] = make_int2(ei[e], __float_as_int(ea[e]));
}

// ---------------------------------------------------------------------------
// Layer 1 gather: thread per node, 7 features, 4-edge unroll
// ---------------------------------------------------------------------------
__global__ void gather7(const float* __restrict__ x, const float* __restrict__ We,
                        const float* __restrict__ be) {
    int n = blockIdx.x * blockDim.x + threadIdx.x;
    if (n >= NNODES) return;
    float w[NFEAT], bb[NFEAT], acc[NFEAT];
#pragma unroll
    for (int f = 0; f < NFEAT; f++) { w[f] = __ldg(&We[f]); bb[f] = __ldg(&be[f]); }
#pragma unroll
    for (int f = 0; f < NFEAT; f++) acc[f] = x[n * NFEAT + f];
    int beg = g_rowptr[n], end = g_rowptr[n + 1];
    int e = beg;
    for (; e + 3 < end; e += 4) {
        int2 p0 = __ldg(&g_epack[e]),     p1 = __ldg(&g_epack[e + 1]);
        int2 p2 = __ldg(&g_epack[e + 2]), p3 = __ldg(&g_epack[e + 3]);
        float a0 = __int_as_float(p0.y), a1 = __int_as_float(p1.y);
        float a2 = __int_as_float(p2.y), a3 = __int_as_float(p3.y);
        float v0[NFEAT], v1[NFEAT], v2[NFEAT], v3[NFEAT];
#pragma unroll
        for (int f = 0; f < NFEAT; f++) v0[f] = __ldg(&x[p0.x * NFEAT + f]);
#pragma unroll
        for (int f = 0; f < NFEAT; f++) v1[f] = __ldg(&x[p1.x * NFEAT + f]);
#pragma unroll
        for (int f = 0; f < NFEAT; f++) v2[f] = __ldg(&x[p2.x * NFEAT + f]);
#pragma unroll
        for (int f = 0; f < NFEAT; f++) v3[f] = __ldg(&x[p3.x * NFEAT + f]);
#pragma unroll
        for (int f = 0; f < NFEAT; f++) {
            acc[f] += fmaxf(v0[f] + fmaf(a0, w[f], bb[f]), 0.f)
                    + fmaxf(v1[f] + fmaf(a1, w[f], bb[f]), 0.f)
                    + fmaxf(v2[f] + fmaf(a2, w[f], bb[f]), 0.f)
                    + fmaxf(v3[f] + fmaf(a3, w[f], bb[f]), 0.f);
        }
    }
    for (; e < end; e++) {
        int2 p = __ldg(&g_epack[e]);
        float a = __int_as_float(p.y);
#pragma unroll
        for (int f = 0; f < NFEAT; f++)
            acc[f] += fmaxf(__ldg(&x[p.x * NFEAT + f]) + fmaf(a, w[f], bb[f]), 0.f);
    }
#pragma unroll
    for (int f = 0; f < NFEAT; f++) g_agg7[n * NFEAT + f] = acc[f];
}

// ---------------------------------------------------------------------------
// Layer 1 dense: writes fp32 h1 AND fp16 copy (-> g_h16a)
// ---------------------------------------------------------------------------
__global__ void dense7(const float* __restrict__ W, const float* __restrict__ b) {
    __shared__ float sW[NFEAT * HID];
    __shared__ float sb[HID];
    __shared__ float sAgg[256 * NFEAT];
    int t = threadIdx.x;  // 0..127
    for (int i = t; i < NFEAT * HID; i += 128) sW[i] = W[i];
    sb[t] = b[t];

    int n0 = blockIdx.x * 256;
    int cnt = NNODES - n0; if (cnt > 256) cnt = 256;
    for (int i = t; i < cnt * NFEAT; i += 128) sAgg[i] = g_agg7[n0 * NFEAT + i];
    __syncthreads();

    for (int r = 0; r < cnt; r++) {
        float acc = sb[t];
#pragma unroll
        for (int k = 0; k < NFEAT; k++)
            acc = fmaf(sAgg[r * NFEAT + k], sW[k * HID + t], acc);
        float o = fmaxf(acc, 0.f);
        size_t idx = (size_t)(n0 + r) * HID + t;
        g_ha[idx]   = o;
        g_h16a[idx] = __float2half_rn(o);
    }
}

// ---------------------------------------------------------------------------
// FUSED GINE layer (128 feats): gather (warp-per-node, fp16 rows, 8-edge
// unroll) directly into smem A-tile, then FFMA dense on the tile.
// h16in is READ-ONLY this launch; fp16 output goes to h16out (double buffer).
// Block: 256 thr / 8 warps, 64 nodes. smem = 96KB -> 2 CTAs/SM; one CTA's
// latency-bound gather overlaps the other's FFMA dense.
// ---------------------------------------------------------------------------
__device__ __forceinline__ void acc_edge(float4& acc, uint2 v, float a,
                                         const float4& w, const float4& bb) {
    __half2 h0 = *reinterpret_cast<__half2*>(&v.x);
    __half2 h1 = *reinterpret_cast<__half2*>(&v.y);
    float2 f0 = __half22float2(h0);
    float2 f1 = __half22float2(h1);
    acc.x += fmaxf(f0.x + fmaf(a, w.x, bb.x), 0.f);
    acc.y += fmaxf(f0.y + fmaf(a, w.y, bb.y), 0.f);
    acc.z += fmaxf(f1.x + fmaf(a, w.z, bb.z), 0.f);
    acc.w += fmaxf(f1.y + fmaf(a, w.w, bb.w), 0.f);
}

__global__ void __launch_bounds__(256, 2)
gine_layer(const float* __restrict__ h32, const __half* __restrict__ h16in,
           const float* __restrict__ We, const float* __restrict__ be,
           const float* __restrict__ W, const float* __restrict__ b,
           float* __restrict__ out, __half* __restrict__ h16out) {
    extern __shared__ float sm[];
    float* sW = sm;              // 128*128 = 64KB
    float* sA = sm + HID * HID;  // 64*128  = 32KB
    int t = threadIdx.x;
    int lane = t & 31, wid = t >> 5;
    int m0 = blockIdx.x * 64;

    // Stage W (pipelines with gather's loads)
    {
        float4* dW = (float4*)sW;
        const float4* gW = (const float4*)W;
        for (int i = t; i < HID * HID / 4; i += 256) dW[i] = gW[i];
    }

    // Gather phase: warp wid handles nodes m0+wid*8 .. +7
    {
        float4 w  = __ldg(&((const float4*)We)[lane]);
        float4 bb = __ldg(&((const float4*)be)[lane]);
        const uint2* h16 = (const uint2*)h16in;
        for (int r = wid * 8; r < wid * 8 + 8; r++) {
            int n = m0 + r;
            float4 acc = make_float4(0.f, 0.f, 0.f, 0.f);
            if (n < NNODES) {
                acc = ((const float4*)h32)[(size_t)n * 32 + lane];  // self term
                int beg = __ldg(&g_rowptr[n]);
                int end = __ldg(&g_rowptr[n + 1]);
                int e = beg;
                for (; e + 7 < end; e += 8) {
                    int2 p[8];
#pragma unroll
                    for (int i = 0; i < 8; i++) p[i] = __ldg(&g_epack[e + i]);
                    uint2 v[8];
#pragma unroll
                    for (int i = 0; i < 8; i++)
                        v[i] = __ldg(&h16[(size_t)p[i].x * 32 + lane]);
#pragma unroll
                    for (int i = 0; i < 8; i++)
                        acc_edge(acc, v[i], __int_as_float(p[i].y), w, bb);
                }
                for (; e + 1 < end; e += 2) {
                    int2 p0 = __ldg(&g_epack[e]), p1 = __ldg(&g_epack[e + 1]);
                    uint2 v0 = __ldg(&h16[(size_t)p0.x * 32 + lane]);
                    uint2 v1 = __ldg(&h16[(size_t)p1.x * 32 + lane]);
                    acc_edge(acc, v0, __int_as_float(p0.y), w, bb);
                    acc_edge(acc, v1, __int_as_float(p1.y), w, bb);
                }
                if (e < end) {
                    int2 p0 = __ldg(&g_epack[e]);
                    uint2 v0 = __ldg(&h16[(size_t)p0.x * 32 + lane]);
                    acc_edge(acc, v0, __int_as_float(p0.y), w, bb);
                }
            }
            *(float4*)(sA + r * HID + lane * 4) = acc;
        }
    }
    __syncthreads();

    // Dense phase: 8x4 register block per thread (proven FFMA kernel)
    int tn = t & 31;
    int tm = t >> 5;
    float acc[8][4];
#pragma unroll
    for (int i = 0; i < 8; i++)
#pragma unroll
        for (int j = 0; j < 4; j++) acc[i][j] = 0.f;

#pragma unroll 8
    for (int k4 = 0; k4 < 32; k4++) {
        float4 a4[8];
#pragma unroll
        for (int i = 0; i < 8; i++)
            a4[i] = ((float4*)(sA + (tm * 8 + i) * HID))[k4];
#pragma unroll
        for (int kk = 0; kk < 4; kk++) {
            float4 w4 = ((float4*)(sW + (k4 * 4 + kk) * HID))[tn];
#pragma unroll
            for (int i = 0; i < 8; i++) {
                float av = (kk == 0) ? a4[i].x : (kk == 1) ? a4[i].y
                         : (kk == 2) ? a4[i].z : a4[i].w;
                acc[i][0] = fmaf(av, w4.x, acc[i][0]);
                acc[i][1] = fmaf(av, w4.y, acc[i][1]);
                acc[i][2] = fmaf(av, w4.z, acc[i][2]);
                acc[i][3] = fmaf(av, w4.w, acc[i][3]);
            }
        }
    }

    float4 bb4 = __ldg(&((const float4*)b)[tn]);
#pragma unroll
    for (int i = 0; i < 8; i++) {
        int n = m0 + tm * 8 + i;
        if (n < NNODES) {
            float4 o;
            o.x = fmaxf(acc[i][0] + bb4.x, 0.f);
            o.y = fmaxf(acc[i][1] + bb4.y, 0.f);
            o.z = fmaxf(acc[i][2] + bb4.z, 0.f);
            o.w = fmaxf(acc[i][3] + bb4.w, 0.f);
            ((float4*)out)[(size_t)n * 32 + tn] = o;
            if (h16out) {
                uint2 hv;
                __half2 p0 = __floats2half2_rn(o.x, o.y);
                __half2 p1 = __floats2half2_rn(o.z, o.w);
                hv.x = *reinterpret_cast<unsigned*>(&p0);
                hv.y = *reinterpret_cast<unsigned*>(&p1);
                ((uint2*)h16out)[(size_t)n * 32 + tn] = hv;
            }
        }
    }
}

// ---------------------------------------------------------------------------
// Pooling + head
// ---------------------------------------------------------------------------
__global__ void pool_init() {
    int t = blockIdx.x * blockDim.x + threadIdx.x;
    if (t < NGRAPH * HID) g_pool[t] = 0.f;
    if (t < NGRAPH) g_cnt[t] = 0.f;
}

__global__ void pool_kernel(const float* __restrict__ h, const int* __restrict__ batch) {
    int f = threadIdx.x;  // 0..127
    int n0 = blockIdx.x * 256;
    int n1 = n0 + 256; if (n1 > NNODES) n1 = NNODES;
    if (n0 >= NNODES) return;
    float acc = 0.f, c = 0.f;
    int curg = batch[n0];
    for (int n = n0; n < n1; n++) {
        int g = batch[n];
        if (g != curg) {
            atomicAdd(&g_pool[curg * HID + f], acc);
            if (f == 0) atomicAdd(&g_cnt[curg], c);
            acc = 0.f; c = 0.f; curg = g;
        }
        acc += h[(size_t)n * HID + f];
        c += 1.f;
    }
    atomicAdd(&g_pool[curg * HID + f], acc);
    if (f == 0) atomicAdd(&g_cnt[curg], c);
}

__global__ void final_kernel(const float* __restrict__ Wlin, const float* __restrict__ blin,
                             float* __restrict__ out) {
    int t = threadIdx.x;
    if (t >= NGRAPH * NCLASS) return;
    int g = t / NCLASS, c = t % NCLASS;
    float cnt = fmaxf(g_cnt[g], 1.f);
    float acc = blin[c];
#pragma unroll 8
    for (int f = 0; f < HID; f++)
        acc = fmaf(g_pool[g * HID + f] / cnt, Wlin[f * NCLASS + c], acc);
    out[t] = acc;
}

// ---------------------------------------------------------------------------
// Launch
// ---------------------------------------------------------------------------
extern "C" void kernel_launch(void* const* d_in, const int* in_sizes, int n_in,
                              void* d_out, int out_size) {
    const float* x     = (const float*)d_in[0];
    const int*   ei    = (const int*)d_in[1];
    const float* ea    = (const float*)d_in[2];
    const int*   batch = (const int*)d_in[3];
    const float* We1 = (const float*)d_in[4],  *be1 = (const float*)d_in[5];
    const float* W1  = (const float*)d_in[6],  *b1  = (const float*)d_in[7];
    const float* We2 = (const float*)d_in[8],  *be2 = (const float*)d_in[9];
    const float* W2  = (const float*)d_in[10], *b2  = (const float*)d_in[11];
    const float* We3 = (const float*)d_in[12], *be3 = (const float*)d_in[13];
    const float* W3  = (const float*)d_in[14], *b3  = (const float*)d_in[15];
    const float* Wlin = (const float*)d_in[16], *blin = (const float*)d_in[17];
    float* out = (float*)d_out;

    void *hap, *hbp, *curp, *h16ap, *h16bp;
    cudaGetSymbolAddress(&hap,   g_ha);
    cudaGetSymbolAddress(&hbp,   g_hb);
    cudaGetSymbolAddress(&curp,  g_cur);
    cudaGetSymbolAddress(&h16ap, g_h16a);
    cudaGetSymbolAddress(&h16bp, g_h16b);
    float*  ha   = (float*)hap;
    float*  hb   = (float*)hbp;
    __half* h16a = (__half*)h16ap;
    __half* h16b = (__half*)h16bp;

    cudaFuncSetAttribute(gine_layer, cudaFuncAttributeMaxDynamicSharedMemorySize, 98304);

    const int EBLK = (NEDGES + 255) / 256;
    const int L_BLOCKS = (NNODES + 63) / 64;

    // CSR build (reused by all 3 layers)
    cudaMemsetAsync(curp, 0, NNODES * sizeof(int), 0);
    hist_kernel<<<EBLK, 256>>>(ei);
    scan_kernel<<<1, 1024>>>();
    fill_kernel<<<EBLK, 256>>>(ei, ea);

    // Layer 1 (in = 7 feats)
    gather7<<<(NNODES + 255) / 256, 256>>>(x, We1, be1);
    dense7<<<(NNODES + 255) / 256, 128>>>(W1, b1);          // -> g_ha + g_h16a

    // Layer 2 (fused): reads h16a, writes hb + h16b
    gine_layer<<<L_BLOCKS, 256, 98304>>>(ha, h16a, We2, be2, W2, b2, hb, h16b);

    // Layer 3 (fused): reads h16b, writes ha (no fp16 out)
    gine_layer<<<L_BLOCKS, 256, 98304>>>(hb, h16b, We3, be3, W3, b3, ha, (__half*)0);

    // Mean pool + linear head
    pool_init<<<8, 128>>>();
    pool_kernel<<<(NNODES + 255) / 256, 128>>>(ha, batch);
    final_kernel<<<1, 64>>>(Wlin, blin, out);
}

// round 13
// speedup vs baseline: 1.4321x; 1.4321x over previous
#include <cuda_runtime.h>
#include <cuda_fp16.h>
#include <cstddef>

#define NNODES 100000
#define NEDGES 1600000
#define NFEAT  7
#define HID    128
#define NGRAPH 8
#define NCLASS 5

// ---------------------------------------------------------------------------
// Device-global scratch (allocation-free contract)
// ---------------------------------------------------------------------------
__device__ int    g_rowptr[NNODES + 1];
__device__ int    g_cur[NNODES];
__device__ int2   g_epack[NEDGES];        // CSR slot: {src, attr bits}
__device__ float  g_agg7[NNODES * NFEAT];
__device__ float  g_agg[NNODES * HID];
__device__ float  g_ha[NNODES * HID];
__device__ float  g_hb[NNODES * HID];
__device__ __half g_h16[NNODES * HID];    // fp16 copy of current h (neighbor reads)
__device__ float  g_pool[NGRAPH * HID];
__device__ float  g_cnt[NGRAPH];

// ---------------------------------------------------------------------------
// CSR build: histogram -> scan -> fill
// ---------------------------------------------------------------------------
__global__ void hist_kernel(const int* __restrict__ ei) {
    int e = blockIdx.x * blockDim.x + threadIdx.x;
    if (e < NEDGES) atomicAdd(&g_cur[ei[NEDGES + e]], 1);
}

__global__ void scan_kernel() {
    __shared__ int warp_sums[32];
    __shared__ int s_carry;
    int tid = threadIdx.x;
    int lane = tid & 31, wid = tid >> 5;
    if (tid == 0) s_carry = 0;
    __syncthreads();
    for (int base = 0; base < NNODES; base += 1024) {
        int i = base + tid;
        int v = (i < NNODES) ? g_cur[i] : 0;
        int incl = v;
#pragma unroll
        for (int o = 1; o < 32; o <<= 1) {
            int t = __shfl_up_sync(0xffffffffu, incl, o);
            if (lane >= o) incl += t;
        }
        if (lane == 31) warp_sums[wid] = incl;
        __syncthreads();
        if (wid == 0) {
            int ws = warp_sums[lane];
            int wincl = ws;
#pragma unroll
            for (int o = 1; o < 32; o <<= 1) {
                int t = __shfl_up_sync(0xffffffffu, wincl, o);
                if (lane >= o) wincl += t;
            }
            warp_sums[lane] = wincl - ws;
        }
        __syncthreads();
        int excl = incl - v + warp_sums[wid] + s_carry;
        if (i < NNODES) { g_rowptr[i] = excl; g_cur[i] = excl; }
        __syncthreads();
        if (tid == 1023) s_carry = excl + v;
        __syncthreads();
    }
    if (tid == 0) g_rowptr[NNODES] = NEDGES;
}

__global__ void fill_kernel(const int* __restrict__ ei, const float* __restrict__ ea) {
    int e = blockIdx.x * blockDim.x + threadIdx.x;
    if (e >= NEDGES) return;
    int d = ei[NEDGES + e];
    int pos = atomicAdd(&g_cur[d], 1);
    g_epack[pos] = make_int2(ei[e], __float_as_int(ea[e]));
}

// ---------------------------------------------------------------------------
// Layer 1 gather: thread per node, 7 features, 4-edge unroll
// ---------------------------------------------------------------------------
__global__ void gather7(const float* __restrict__ x, const float* __restrict__ We,
                        const float* __restrict__ be) {
    int n = blockIdx.x * blockDim.x + threadIdx.x;
    if (n >= NNODES) return;
    float w[NFEAT], bb[NFEAT], acc[NFEAT];
#pragma unroll
    for (int f = 0; f < NFEAT; f++) { w[f] = __ldg(&We[f]); bb[f] = __ldg(&be[f]); }
#pragma unroll
    for (int f = 0; f < NFEAT; f++) acc[f] = x[n * NFEAT + f];
    int beg = g_rowptr[n], end = g_rowptr[n + 1];
    int e = beg;
    for (; e + 3 < end; e += 4) {
        int2 p0 = __ldg(&g_epack[e]),     p1 = __ldg(&g_epack[e + 1]);
        int2 p2 = __ldg(&g_epack[e + 2]), p3 = __ldg(&g_epack[e + 3]);
        float a0 = __int_as_float(p0.y), a1 = __int_as_float(p1.y);
        float a2 = __int_as_float(p2.y), a3 = __int_as_float(p3.y);
        float v0[NFEAT], v1[NFEAT], v2[NFEAT], v3[NFEAT];
#pragma unroll
        for (int f = 0; f < NFEAT; f++) v0[f] = __ldg(&x[p0.x * NFEAT + f]);
#pragma unroll
        for (int f = 0; f < NFEAT; f++) v1[f] = __ldg(&x[p1.x * NFEAT + f]);
#pragma unroll
        for (int f = 0; f < NFEAT; f++) v2[f] = __ldg(&x[p2.x * NFEAT + f]);
#pragma unroll
        for (int f = 0; f < NFEAT; f++) v3[f] = __ldg(&x[p3.x * NFEAT + f]);
#pragma unroll
        for (int f = 0; f < NFEAT; f++) {
            acc[f] += fmaxf(v0[f] + fmaf(a0, w[f], bb[f]), 0.f)
                    + fmaxf(v1[f] + fmaf(a1, w[f], bb[f]), 0.f)
                    + fmaxf(v2[f] + fmaf(a2, w[f], bb[f]), 0.f)
                    + fmaxf(v3[f] + fmaf(a3, w[f], bb[f]), 0.f);
        }
    }
    for (; e < end; e++) {
        int2 p = __ldg(&g_epack[e]);
        float a = __int_as_float(p.y);
#pragma unroll
        for (int f = 0; f < NFEAT; f++)
            acc[f] += fmaxf(__ldg(&x[p.x * NFEAT + f]) + fmaf(a, w[f], bb[f]), 0.f);
    }
#pragma unroll
    for (int f = 0; f < NFEAT; f++) g_agg7[n * NFEAT + f] = acc[f];
}

// ---------------------------------------------------------------------------
// Layer 1 dense: writes fp32 h1 AND fp16 copy
// ---------------------------------------------------------------------------
__global__ void dense7(const float* __restrict__ W, const float* __restrict__ b) {
    __shared__ float sW[NFEAT * HID];
    __shared__ float sb[HID];
    __shared__ float sAgg[256 * NFEAT];
    int t = threadIdx.x;  // 0..127
    for (int i = t; i < NFEAT * HID; i += 128) sW[i] = W[i];
    sb[t] = b[t];

    int n0 = blockIdx.x * 256;
    int cnt = NNODES - n0; if (cnt > 256) cnt = 256;
    for (int i = t; i < cnt * NFEAT; i += 128) sAgg[i] = g_agg7[n0 * NFEAT + i];
    __syncthreads();

    for (int r = 0; r < cnt; r++) {
        float acc = sb[t];
#pragma unroll
        for (int k = 0; k < NFEAT; k++)
            acc = fmaf(sAgg[r * NFEAT + k], sW[k * HID + t], acc);
        float o = fmaxf(acc, 0.f);
        size_t idx = (size_t)(n0 + r) * HID + t;
        g_ha[idx]  = o;
        g_h16[idx] = __float2half_rn(o);
    }
}

// ---------------------------------------------------------------------------
// 128-feat gather: TWO warps per node, fp16 rows, 8-edge groups interleaved.
// sub-warp 0 takes groups 0,2,4..., sub-warp 1 takes 1,3,5...; partials
// combined via smem. Doubles concurrent latency chains per node.
// ---------------------------------------------------------------------------
__device__ __forceinline__ void acc_edge(float4& acc, uint2 v, float a,
                                         const float4& w, const float4& bb) {
    __half2 h0 = *reinterpret_cast<__half2*>(&v.x);
    __half2 h1 = *reinterpret_cast<__half2*>(&v.y);
    float2 f0 = __half22float2(h0);
    float2 f1 = __half22float2(h1);
    acc.x += fmaxf(f0.x + fmaf(a, w.x, bb.x), 0.f);
    acc.y += fmaxf(f0.y + fmaf(a, w.y, bb.y), 0.f);
    acc.z += fmaxf(f1.x + fmaf(a, w.z, bb.z), 0.f);
    acc.w += fmaxf(f1.y + fmaf(a, w.w, bb.w), 0.f);
}

__global__ void __launch_bounds__(256)
gather128(const float* __restrict__ h32, const float* __restrict__ We,
          const float* __restrict__ be, float* __restrict__ aggout) {
    __shared__ float4 part[4][32];
    int t = threadIdx.x;
    int lane = t & 31, wid = t >> 5;
    int slot = wid >> 1;                 // 0..3: node slot within block
    int sub  = wid & 1;                  // 0/1: which half of the edge groups
    int node = blockIdx.x * 4 + slot;

    float4 acc = make_float4(0.f, 0.f, 0.f, 0.f);
    if (node < NNODES) {
        float4 w  = __ldg(&((const float4*)We)[lane]);
        float4 bb = __ldg(&((const float4*)be)[lane]);
        const uint2* h16 = (const uint2*)g_h16;
        int beg = __ldg(&g_rowptr[node]);
        int end = __ldg(&g_rowptr[node + 1]);
        if (sub == 0)
            acc = ((const float4*)h32)[(size_t)node * 32 + lane];  // self term

        for (int e0 = beg + sub * 8; e0 < end; e0 += 16) {
            int m = end - e0; if (m > 8) m = 8;
            if (m == 8) {
                int2 p[8];
#pragma unroll
                for (int i = 0; i < 8; i++) p[i] = __ldg(&g_epack[e0 + i]);
                uint2 v[8];
#pragma unroll
                for (int i = 0; i < 8; i++)
                    v[i] = __ldg(&h16[(size_t)p[i].x * 32 + lane]);
#pragma unroll
                for (int i = 0; i < 8; i++)
                    acc_edge(acc, v[i], __int_as_float(p[i].y), w, bb);
            } else {
                int i = 0;
                for (; i + 1 < m; i += 2) {
                    int2 p0 = __ldg(&g_epack[e0 + i]), p1 = __ldg(&g_epack[e0 + i + 1]);
                    uint2 v0 = __ldg(&h16[(size_t)p0.x * 32 + lane]);
                    uint2 v1 = __ldg(&h16[(size_t)p1.x * 32 + lane]);
                    acc_edge(acc, v0, __int_as_float(p0.y), w, bb);
                    acc_edge(acc, v1, __int_as_float(p1.y), w, bb);
                }
                if (i < m) {
                    int2 p0 = __ldg(&g_epack[e0 + i]);
                    uint2 v0 = __ldg(&h16[(size_t)p0.x * 32 + lane]);
                    acc_edge(acc, v0, __int_as_float(p0.y), w, bb);
                }
            }
        }
        if (sub == 1) part[slot][lane] = acc;
    }
    __syncthreads();
    if (node < NNODES && sub == 0) {
        float4 p = part[slot][lane];
        acc.x += p.x; acc.y += p.y; acc.z += p.z; acc.w += p.w;
        ((float4*)aggout)[(size_t)node * 32 + lane] = acc;
    }
}

// ---------------------------------------------------------------------------
// Dense 128x128 FFMA (known-good): out[n,:] = relu( A[n,:] @ W + b )
// Tile: 64 nodes x 128 outs, 256 threads, 8x4 register block, W+A in smem
// ---------------------------------------------------------------------------
__global__ void dense128(const float* __restrict__ A, const float* __restrict__ W,
                         const float* __restrict__ b, float* __restrict__ out,
                         int write16) {
    extern __shared__ float sm[];
    float* sW = sm;              // 64KB
    float* sA = sm + HID * HID;  // 32KB
    int t = threadIdx.x;         // 0..255
    int m0 = blockIdx.x * 64;

    {
        float4* dW = (float4*)sW;
        const float4* gW = (const float4*)W;
        for (int i = t; i < HID * HID / 4; i += 256) dW[i] = gW[i];
    }
    {
        float4* dA = (float4*)sA;
        for (int i = t; i < 64 * 32; i += 256) {
            int r = i >> 5, c = i & 31;
            int n = m0 + r;
            float4 v = make_float4(0.f, 0.f, 0.f, 0.f);
            if (n < NNODES) v = ((const float4*)A)[(size_t)n * 32 + c];
            dA[i] = v;
        }
    }
    __syncthreads();

    int tn = t & 31;
    int tm = t >> 5;
    float acc[8][4];
#pragma unroll
    for (int i = 0; i < 8; i++)
#pragma unroll
        for (int j = 0; j < 4; j++) acc[i][j] = 0.f;

#pragma unroll 8
    for (int k4 = 0; k4 < 32; k4++) {
        float4 a4[8];
#pragma unroll
        for (int i = 0; i < 8; i++)
            a4[i] = ((float4*)(sA + (tm * 8 + i) * HID))[k4];
#pragma unroll
        for (int kk = 0; kk < 4; kk++) {
            float4 w4 = ((float4*)(sW + (k4 * 4 + kk) * HID))[tn];
#pragma unroll
            for (int i = 0; i < 8; i++) {
                float av = (kk == 0) ? a4[i].x : (kk == 1) ? a4[i].y
                         : (kk == 2) ? a4[i].z : a4[i].w;
                acc[i][0] = fmaf(av, w4.x, acc[i][0]);
                acc[i][1] = fmaf(av, w4.y, acc[i][1]);
                acc[i][2] = fmaf(av, w4.z, acc[i][2]);
                acc[i][3] = fmaf(av, w4.w, acc[i][3]);
            }
        }
    }

    float4 bb = __ldg(&((const float4*)b)[tn]);
#pragma unroll
    for (int i = 0; i < 8; i++) {
        int n = m0 + tm * 8 + i;
        if (n < NNODES) {
            float4 o;
            o.x = fmaxf(acc[i][0] + bb.x, 0.f);
            o.y = fmaxf(acc[i][1] + bb.y, 0.f);
            o.z = fmaxf(acc[i][2] + bb.z, 0.f);
            o.w = fmaxf(acc[i][3] + bb.w, 0.f);
            ((float4*)out)[(size_t)n * 32 + tn] = o;
            if (write16) {
                uint2 hv;
                __half2 p0 = __floats2half2_rn(o.x, o.y);
                __half2 p1 = __floats2half2_rn(o.z, o.w);
                hv.x = *reinterpret_cast<unsigned*>(&p0);
                hv.y = *reinterpret_cast<unsigned*>(&p1);
                ((uint2*)g_h16)[(size_t)n * 32 + tn] = hv;
            }
        }
    }
}

// ---------------------------------------------------------------------------
// Pooling + head
// ---------------------------------------------------------------------------
__global__ void pool_init() {
    int t = blockIdx.x * blockDim.x + threadIdx.x;
    if (t < NGRAPH * HID) g_pool[t] = 0.f;
    if (t < NGRAPH) g_cnt[t] = 0.f;
}

__global__ void pool_kernel(const float* __restrict__ h, const int* __restrict__ batch) {
    int f = threadIdx.x;  // 0..127
    int n0 = blockIdx.x * 256;
    int n1 = n0 + 256; if (n1 > NNODES) n1 = NNODES;
    if (n0 >= NNODES) return;
    float acc = 0.f, c = 0.f;
    int curg = batch[n0];
    for (int n = n0; n < n1; n++) {
        int g = batch[n];
        if (g != curg) {
            atomicAdd(&g_pool[curg * HID + f], acc);
            if (f == 0) atomicAdd(&g_cnt[curg], c);
            acc = 0.f; c = 0.f; curg = g;
        }
        acc += h[(size_t)n * HID + f];
        c += 1.f;
    }
    atomicAdd(&g_pool[curg * HID + f], acc);
    if (f == 0) atomicAdd(&g_cnt[curg], c);
}

__global__ void final_kernel(const float* __restrict__ Wlin, const float* __restrict__ blin,
                             float* __restrict__ out) {
    int t = threadIdx.x;
    if (t >= NGRAPH * NCLASS) return;
    int g = t / NCLASS, c = t % NCLASS;
    float cnt = fmaxf(g_cnt[g], 1.f);
    float acc = blin[c];
#pragma unroll 8
    for (int f = 0; f < HID; f++)
        acc = fmaf(g_pool[g * HID + f] / cnt, Wlin[f * NCLASS + c], acc);
    out[t] = acc;
}

// ---------------------------------------------------------------------------
// Launch
// ---------------------------------------------------------------------------
extern "C" void kernel_launch(void* const* d_in, const int* in_sizes, int n_in,
                              void* d_out, int out_size) {
    const float* x     = (const float*)d_in[0];
    const int*   ei    = (const int*)d_in[1];
    const float* ea    = (const float*)d_in[2];
    const int*   batch = (const int*)d_in[3];
    const float* We1 = (const float*)d_in[4],  *be1 = (const float*)d_in[5];
    const float* W1  = (const float*)d_in[6],  *b1  = (const float*)d_in[7];
    const float* We2 = (const float*)d_in[8],  *be2 = (const float*)d_in[9];
    const float* W2  = (const float*)d_in[10], *b2  = (const float*)d_in[11];
    const float* We3 = (const float*)d_in[12], *be3 = (const float*)d_in[13];
    const float* W3  = (const float*)d_in[14], *b3  = (const float*)d_in[15];
    const float* Wlin = (const float*)d_in[16], *blin = (const float*)d_in[17];
    float* out = (float*)d_out;

    void *aggp, *hap, *hbp, *curp;
    cudaGetSymbolAddress(&aggp, g_agg);
    cudaGetSymbolAddress(&hap,  g_ha);
    cudaGetSymbolAddress(&hbp,  g_hb);
    cudaGetSymbolAddress(&curp, g_cur);
    float* agg = (float*)aggp;
    float* ha  = (float*)hap;
    float* hb  = (float*)hbp;

    cudaFuncSetAttribute(dense128, cudaFuncAttributeMaxDynamicSharedMemorySize, 98304);

    const int EBLK = (NEDGES + 255) / 256;
    const int G128_BLOCKS = (NNODES + 3) / 4;            // 2 warps per node
    const int D128_BLOCKS = (NNODES + 63) / 64;

    // CSR build (reused by all 3 layers)
    cudaMemsetAsync(curp, 0, NNODES * sizeof(int), 0);
    hist_kernel<<<EBLK, 256>>>(ei);
    scan_kernel<<<1, 1024>>>();
    fill_kernel<<<EBLK, 256>>>(ei, ea);

    // Layer 1 (in = 7 feats)
    gather7<<<(NNODES + 255) / 256, 256>>>(x, We1, be1);
    dense7<<<(NNODES + 255) / 256, 128>>>(W1, b1);                // -> g_ha + g_h16

    // Layer 2
    gather128<<<G128_BLOCKS, 256>>>(ha, We2, be2, agg);           // reads g_h16 (h1)
    dense128<<<D128_BLOCKS, 256, 98304>>>(agg, W2, b2, hb, 1);    // -> g_hb + g_h16

    // Layer 3
    gather128<<<G128_BLOCKS, 256>>>(hb, We3, be3, agg);           // reads g_h16 (h2)
    dense128<<<D128_BLOCKS, 256, 98304>>>(agg, W3, b3, ha, 0);    // -> g_ha

    // Mean pool + linear head
    pool_init<<<8, 128>>>();
    pool_kernel<<<(NNODES + 255) / 256, 128>>>(ha, batch);
    final_kernel<<<1, 64>>>(Wlin, blin, out);
}

// round 15
// speedup vs baseline: 1.5764x; 1.1008x over previous
#include <cuda_runtime.h>
#include <cuda_fp16.h>
#include <cstddef>

#define NNODES 100000
#define NEDGES 1600000
#define NFEAT  7
#define HID    128
#define NGRAPH 8
#define NCLASS 5

// ---------------------------------------------------------------------------
// Device-global scratch (allocation-free contract).
// g_cur is zero-initialized at module load and re-zeroed by rezero_kernel at
// the end of every launch sequence, so each kernel_launch call sees zeros.
// ---------------------------------------------------------------------------
__device__ int    g_rowptr[NNODES + 1];
__device__ int    g_cur[NNODES];
__device__ int2   g_epack[NEDGES];        // CSR slot: {src, attr bits}
__device__ float  g_agg[NNODES * HID];
__device__ float  g_ha[NNODES * HID];
__device__ float  g_hb[NNODES * HID];
__device__ __half g_h16[NNODES * HID];    // fp16 copy of current h (neighbor reads)
__device__ float  g_pool[NGRAPH * HID];
__device__ float  g_cnt[NGRAPH];

// ---------------------------------------------------------------------------
// CSR build: histogram -> scan -> fill  (g_cur pre-zeroed)
// ---------------------------------------------------------------------------
__global__ void hist_kernel(const int* __restrict__ ei) {
    int e = blockIdx.x * blockDim.x + threadIdx.x;
    if (e < NEDGES) atomicAdd(&g_cur[ei[NEDGES + e]], 1);
}

__global__ void scan_kernel() {
    __shared__ int warp_sums[32];
    __shared__ int s_carry;
    int tid = threadIdx.x;
    int lane = tid & 31, wid = tid >> 5;
    if (tid == 0) s_carry = 0;
    __syncthreads();
    for (int base = 0; base < NNODES; base += 1024) {
        int i = base + tid;
        int v = (i < NNODES) ? g_cur[i] : 0;
        int incl = v;
#pragma unroll
        for (int o = 1; o < 32; o <<= 1) {
            int t = __shfl_up_sync(0xffffffffu, incl, o);
            if (lane >= o) incl += t;
        }
        if (lane == 31) warp_sums[wid] = incl;
        __syncthreads();
        if (wid == 0) {
            int ws = warp_sums[lane];
            int wincl = ws;
#pragma unroll
            for (int o = 1; o < 32; o <<= 1) {
                int t = __shfl_up_sync(0xffffffffu, wincl, o);
                if (lane >= o) wincl += t;
            }
            warp_sums[lane] = wincl - ws;
        }
        __syncthreads();
        int excl = incl - v + warp_sums[wid] + s_carry;
        if (i < NNODES) { g_rowptr[i] = excl; g_cur[i] = excl; }
        __syncthreads();
        if (tid == 1023) s_carry = excl + v;
        __syncthreads();
    }
    if (tid == 0) g_rowptr[NNODES] = NEDGES;
}

__global__ void fill_kernel(const int* __restrict__ ei, const float* __restrict__ ea) {
    int e = blockIdx.x * blockDim.x + threadIdx.x;
    if (e >= NEDGES) return;
    int d = ei[NEDGES + e];
    int pos = atomicAdd(&g_cur[d], 1);
    g_epack[pos] = make_int2(ei[e], __float_as_int(ea[e]));
}

// Restore g_cur to zero for the next replay (keeps launches deterministic).
__global__ void rezero_kernel() {
    int i = blockIdx.x * blockDim.x + threadIdx.x;
    if (i < NNODES) g_cur[i] = 0;
}

// ---------------------------------------------------------------------------
// FUSED layer 1: per-thread 7-feat gather into smem, then dense 7->128.
// Block: 128 threads, 128 nodes. Writes fp32 h1 AND fp16 mirror.
// ---------------------------------------------------------------------------
__global__ void gine7(const float* __restrict__ x, const float* __restrict__ We,
                      const float* __restrict__ be, const float* __restrict__ W,
                      const float* __restrict__ b) {
    __shared__ float sW[NFEAT * HID];
    __shared__ float sb[HID];
    __shared__ float sAgg[128 * NFEAT];
    int t = threadIdx.x;  // 0..127
    for (int i = t; i < NFEAT * HID; i += 128) sW[i] = W[i];
    sb[t] = b[t];

    int n0 = blockIdx.x * 128;
    int n  = n0 + t;

    // Phase 1: gather (thread-per-node, 4-edge unroll)
    if (n < NNODES) {
        float w[NFEAT], bb[NFEAT], acc[NFEAT];
#pragma unroll
        for (int f = 0; f < NFEAT; f++) { w[f] = __ldg(&We[f]); bb[f] = __ldg(&be[f]); }
#pragma unroll
        for (int f = 0; f < NFEAT; f++) acc[f] = x[n * NFEAT + f];
        int beg = g_rowptr[n], end = g_rowptr[n + 1];
        int e = beg;
        for (; e + 3 < end; e += 4) {
            int2 p0 = __ldg(&g_epack[e]),     p1 = __ldg(&g_epack[e + 1]);
            int2 p2 = __ldg(&g_epack[e + 2]), p3 = __ldg(&g_epack[e + 3]);
            float a0 = __int_as_float(p0.y), a1 = __int_as_float(p1.y);
            float a2 = __int_as_float(p2.y), a3 = __int_as_float(p3.y);
            float v0[NFEAT], v1[NFEAT], v2[NFEAT], v3[NFEAT];
#pragma unroll
            for (int f = 0; f < NFEAT; f++) v0[f] = __ldg(&x[p0.x * NFEAT + f]);
#pragma unroll
            for (int f = 0; f < NFEAT; f++) v1[f] = __ldg(&x[p1.x * NFEAT + f]);
#pragma unroll
            for (int f = 0; f < NFEAT; f++) v2[f] = __ldg(&x[p2.x * NFEAT + f]);
#pragma unroll
            for (int f = 0; f < NFEAT; f++) v3[f] = __ldg(&x[p3.x * NFEAT + f]);
#pragma unroll
            for (int f = 0; f < NFEAT; f++) {
                acc[f] += fmaxf(v0[f] + fmaf(a0, w[f], bb[f]), 0.f)
                        + fmaxf(v1[f] + fmaf(a1, w[f], bb[f]), 0.f)
                        + fmaxf(v2[f] + fmaf(a2, w[f], bb[f]), 0.f)
                        + fmaxf(v3[f] + fmaf(a3, w[f], bb[f]), 0.f);
            }
        }
        for (; e < end; e++) {
            int2 p = __ldg(&g_epack[e]);
            float a = __int_as_float(p.y);
#pragma unroll
            for (int f = 0; f < NFEAT; f++)
                acc[f] += fmaxf(__ldg(&x[p.x * NFEAT + f]) + fmaf(a, w[f], bb[f]), 0.f);
        }
#pragma unroll
        for (int f = 0; f < NFEAT; f++) sAgg[t * NFEAT + f] = acc[f];
    }
    __syncthreads();

    // Phase 2: dense (col t, loop over block's rows)
    int cnt = NNODES - n0; if (cnt > 128) cnt = 128;
    for (int r = 0; r < cnt; r++) {
        float acc = sb[t];
#pragma unroll
        for (int k = 0; k < NFEAT; k++)
            acc = fmaf(sAgg[r * NFEAT + k], sW[k * HID + t], acc);
        float o = fmaxf(acc, 0.f);
        size_t idx = (size_t)(n0 + r) * HID + t;
        g_ha[idx]  = o;
        g_h16[idx] = __float2half_rn(o);
    }
}

// ---------------------------------------------------------------------------
// 128-feat gather (R7 best): warp per node, fp16 rows, 8-edge unroll
// ---------------------------------------------------------------------------
__device__ __forceinline__ void acc_edge(float4& acc, uint2 v, float a,
                                         const float4& w, const float4& bb) {
    __half2 h0 = *reinterpret_cast<__half2*>(&v.x);
    __half2 h1 = *reinterpret_cast<__half2*>(&v.y);
    float2 f0 = __half22float2(h0);
    float2 f1 = __half22float2(h1);
    acc.x += fmaxf(f0.x + fmaf(a, w.x, bb.x), 0.f);
    acc.y += fmaxf(f0.y + fmaf(a, w.y, bb.y), 0.f);
    acc.z += fmaxf(f1.x + fmaf(a, w.z, bb.z), 0.f);
    acc.w += fmaxf(f1.y + fmaf(a, w.w, bb.w), 0.f);
}

__global__ void gather128(const float* __restrict__ h32, const float* __restrict__ We,
                          const float* __restrict__ be, float* __restrict__ aggout) {
    int warp = (blockIdx.x * blockDim.x + threadIdx.x) >> 5;
    int lane = threadIdx.x & 31;
    if (warp >= NNODES) return;
    float4 w  = __ldg(&((const float4*)We)[lane]);
    float4 bb = __ldg(&((const float4*)be)[lane]);
    int beg = __ldg(&g_rowptr[warp]);
    int end = __ldg(&g_rowptr[warp + 1]);
    const uint2* h16 = (const uint2*)g_h16;
    float4 acc = ((const float4*)h32)[(size_t)warp * 32 + lane];

    int e = beg;
    for (; e + 7 < end; e += 8) {
        int2 p[8];
#pragma unroll
        for (int i = 0; i < 8; i++) p[i] = __ldg(&g_epack[e + i]);
        uint2 v[8];
#pragma unroll
        for (int i = 0; i < 8; i++) v[i] = __ldg(&h16[(size_t)p[i].x * 32 + lane]);
#pragma unroll
        for (int i = 0; i < 8; i++)
            acc_edge(acc, v[i], __int_as_float(p[i].y), w, bb);
    }
    for (; e + 1 < end; e += 2) {
        int2 p0 = __ldg(&g_epack[e]), p1 = __ldg(&g_epack[e + 1]);
        uint2 v0 = __ldg(&h16[(size_t)p0.x * 32 + lane]);
        uint2 v1 = __ldg(&h16[(size_t)p1.x * 32 + lane]);
        acc_edge(acc, v0, __int_as_float(p0.y), w, bb);
        acc_edge(acc, v1, __int_as_float(p1.y), w, bb);
    }
    if (e < end) {
        int2 p0 = __ldg(&g_epack[e]);
        uint2 v0 = __ldg(&h16[(size_t)p0.x * 32 + lane]);
        acc_edge(acc, v0, __int_as_float(p0.y), w, bb);
    }
    ((float4*)aggout)[(size_t)warp * 32 + lane] = acc;
}

// ---------------------------------------------------------------------------
// Dense 128x128 FFMA (known-good): out[n,:] = relu( A[n,:] @ W + b )
// ---------------------------------------------------------------------------
__global__ void dense128(const float* __restrict__ A, const float* __restrict__ W,
                         const float* __restrict__ b, float* __restrict__ out,
                         int write16) {
    extern __shared__ float sm[];
    float* sW = sm;              // 64KB
    float* sA = sm + HID * HID;  // 32KB
    int t = threadIdx.x;         // 0..255
    int m0 = blockIdx.x * 64;

    {
        float4* dW = (float4*)sW;
        const float4* gW = (const float4*)W;
        for (int i = t; i < HID * HID / 4; i += 256) dW[i] = gW[i];
    }
    {
        float4* dA = (float4*)sA;
        for (int i = t; i < 64 * 32; i += 256) {
            int r = i >> 5, c = i & 31;
            int n = m0 + r;
            float4 v = make_float4(0.f, 0.f, 0.f, 0.f);
            if (n < NNODES) v = ((const float4*)A)[(size_t)n * 32 + c];
            dA[i] = v;
        }
    }
    __syncthreads();

    int tn = t & 31;
    int tm = t >> 5;
    float acc[8][4];
#pragma unroll
    for (int i = 0; i < 8; i++)
#pragma unroll
        for (int j = 0; j < 4; j++) acc[i][j] = 0.f;

#pragma unroll 8
    for (int k4 = 0; k4 < 32; k4++) {
        float4 a4[8];
#pragma unroll
        for (int i = 0; i < 8; i++)
            a4[i] = ((float4*)(sA + (tm * 8 + i) * HID))[k4];
#pragma unroll
        for (int kk = 0; kk < 4; kk++) {
            float4 w4 = ((float4*)(sW + (k4 * 4 + kk) * HID))[tn];
#pragma unroll
            for (int i = 0; i < 8; i++) {
                float av = (kk == 0) ? a4[i].x : (kk == 1) ? a4[i].y
                         : (kk == 2) ? a4[i].z : a4[i].w;
                acc[i][0] = fmaf(av, w4.x, acc[i][0]);
                acc[i][1] = fmaf(av, w4.y, acc[i][1]);
                acc[i][2] = fmaf(av, w4.z, acc[i][2]);
                acc[i][3] = fmaf(av, w4.w, acc[i][3]);
            }
        }
    }

    float4 bb = __ldg(&((const float4*)b)[tn]);
#pragma unroll
    for (int i = 0; i < 8; i++) {
        int n = m0 + tm * 8 + i;
        if (n < NNODES) {
            float4 o;
            o.x = fmaxf(acc[i][0] + bb.x, 0.f);
            o.y = fmaxf(acc[i][1] + bb.y, 0.f);
            o.z = fmaxf(acc[i][2] + bb.z, 0.f);
            o.w = fmaxf(acc[i][3] + bb.w, 0.f);
            ((float4*)out)[(size_t)n * 32 + tn] = o;
            if (write16) {
                uint2 hv;
                __half2 p0 = __floats2half2_rn(o.x, o.y);
                __half2 p1 = __floats2half2_rn(o.z, o.w);
                hv.x = *reinterpret_cast<unsigned*>(&p0);
                hv.y = *reinterpret_cast<unsigned*>(&p1);
                ((uint2*)g_h16)[(size_t)n * 32 + tn] = hv;
            }
        }
    }
}

// ---------------------------------------------------------------------------
// Pooling + head
// ---------------------------------------------------------------------------
__global__ void pool_init() {
    int t = blockIdx.x * blockDim.x + threadIdx.x;
    if (t < NGRAPH * HID) g_pool[t] = 0.f;
    if (t < NGRAPH) g_cnt[t] = 0.f;
}

__global__ void pool_kernel(const float* __restrict__ h, const int* __restrict__ batch) {
    int f = threadIdx.x;  // 0..127
    int n0 = blockIdx.x * 256;
    int n1 = n0 + 256; if (n1 > NNODES) n1 = NNODES;
    if (n0 >= NNODES) return;
    float acc = 0.f, c = 0.f;
    int curg = batch[n0];
    for (int n = n0; n < n1; n++) {
        int g = batch[n];
        if (g != curg) {
            atomicAdd(&g_pool[curg * HID + f], acc);
            if (f == 0) atomicAdd(&g_cnt[curg], c);
            acc = 0.f; c = 0.f; curg = g;
        }
        acc += h[(size_t)n * HID + f];
        c += 1.f;
    }
    atomicAdd(&g_pool[curg * HID + f], acc);
    if (f == 0) atomicAdd(&g_cnt[curg], c);
}

__global__ void final_kernel(const float* __restrict__ Wlin, const float* __restrict__ blin,
                             float* __restrict__ out) {
    int t = threadIdx.x;
    if (t >= NGRAPH * NCLASS) return;
    int g = t / NCLASS, c = t % NCLASS;
    float cnt = fmaxf(g_cnt[g], 1.f);
    float acc = blin[c];
#pragma unroll 8
    for (int f = 0; f < HID; f++)
        acc = fmaf(g_pool[g * HID + f] / cnt, Wlin[f * NCLASS + c], acc);
    out[t] = acc;
}

// ---------------------------------------------------------------------------
// Launch
// ---------------------------------------------------------------------------
extern "C" void kernel_launch(void* const* d_in, const int* in_sizes, int n_in,
                              void* d_out, int out_size) {
    const float* x     = (const float*)d_in[0];
    const int*   ei    = (const int*)d_in[1];
    const float* ea    = (const float*)d_in[2];
    const int*   batch = (const int*)d_in[3];
    const float* We1 = (const float*)d_in[4],  *be1 = (const float*)d_in[5];
    const float* W1  = (const float*)d_in[6],  *b1  = (const float*)d_in[7];
    const float* We2 = (const float*)d_in[8],  *be2 = (const float*)d_in[9];
    const float* W2  = (const float*)d_in[10], *b2  = (const float*)d_in[11];
    const float* We3 = (const float*)d_in[12], *be3 = (const float*)d_in[13];
    const float* W3  = (const float*)d_in[14], *b3  = (const float*)d_in[15];
    const float* Wlin = (const float*)d_in[16], *blin = (const float*)d_in[17];
    float* out = (float*)d_out;

    void *aggp, *hap, *hbp;
    cudaGetSymbolAddress(&aggp, g_agg);
    cudaGetSymbolAddress(&hap,  g_ha);
    cudaGetSymbolAddress(&hbp,  g_hb);
    float* agg = (float*)aggp;
    float* ha  = (float*)hap;
    float* hb  = (float*)hbp;

    cudaFuncSetAttribute(dense128, cudaFuncAttributeMaxDynamicSharedMemorySize, 98304);

    const int EBLK = (NEDGES + 255) / 256;
    const int G128_BLOCKS = (NNODES * 32 + 255) / 256;   // warp per node
    const int D128_BLOCKS = (NNODES + 63) / 64;

    // CSR build (g_cur enters zeroed: static init on first call, rezero after)
    hist_kernel<<<EBLK, 256>>>(ei);                               // launch 0
    scan_kernel<<<1, 1024>>>();                                   // launch 1
    fill_kernel<<<EBLK, 256>>>(ei, ea);                           // launch 2

    // Layer 1 fused (7-feat gather + dense)
    gine7<<<(NNODES + 127) / 128, 128>>>(x, We1, be1, W1, b1);    // launch 3 -> ha+h16

    // Layer 2 (gather128 now sits at the ncu capture slot)
    gather128<<<G128_BLOCKS, 256>>>(ha, We2, be2, agg);           // launch 4
    dense128<<<D128_BLOCKS, 256, 98304>>>(agg, W2, b2, hb, 1);    // launch 5

    // Layer 3
    gather128<<<G128_BLOCKS, 256>>>(hb, We3, be3, agg);
    dense128<<<D128_BLOCKS, 256, 98304>>>(agg, W3, b3, ha, 0);

    // Mean pool + linear head
    pool_init<<<8, 128>>>();
    pool_kernel<<<(NNODES + 255) / 256, 128>>>(ha, batch);
    final_kernel<<<1, 64>>>(Wlin, blin, out);

    // Restore g_cur = 0 for the next (re)play
    rezero_kernel<<<(NNODES + 255) / 256, 256>>>();
}

// round 17
// speedup vs baseline: 1.8276x; 1.1593x over previous
#include <cuda_runtime.h>
#include <cuda_fp16.h>
#include <cstdint>
#include <cstddef>

#define NNODES 100000
#define NEDGES 1600000
#define NFEAT  7
#define HID    128
#define NGRAPH 8
#define NCLASS 5

// ---------------------------------------------------------------------------
// Device-global scratch
// ---------------------------------------------------------------------------
__device__ int    g_rowptr[NNODES + 1];
__device__ int    g_cur[NNODES];
__device__ int2   g_epack[NEDGES];
__device__ float  g_agg[NNODES * HID];
__device__ float  g_ha[NNODES * HID];
__device__ float  g_hb[NNODES * HID];
__device__ __half g_h16[NNODES * HID];
__device__ float  g_pool[NGRAPH * HID];
__device__ float  g_cnt[NGRAPH];

// ---------------------------------------------------------------------------
// CSR build: histogram -> scan -> fill  (g_cur pre-zeroed; rezero at end)
// ---------------------------------------------------------------------------
__global__ void hist_kernel(const int* __restrict__ ei) {
    int e = blockIdx.x * blockDim.x + threadIdx.x;
    if (e < NEDGES) atomicAdd(&g_cur[ei[NEDGES + e]], 1);
}

__global__ void scan_kernel() {
    __shared__ int warp_sums[32];
    __shared__ int s_carry;
    int tid = threadIdx.x;
    int lane = tid & 31, wid = tid >> 5;
    if (tid == 0) s_carry = 0;
    __syncthreads();
    for (int base = 0; base < NNODES; base += 1024) {
        int i = base + tid;
        int v = (i < NNODES) ? g_cur[i] : 0;
        int incl = v;
#pragma unroll
        for (int o = 1; o < 32; o <<= 1) {
            int t = __shfl_up_sync(0xffffffffu, incl, o);
            if (lane >= o) incl += t;
        }
        if (lane == 31) warp_sums[wid] = incl;
        __syncthreads();
        if (wid == 0) {
            int ws = warp_sums[lane];
            int wincl = ws;
#pragma unroll
            for (int o = 1; o < 32; o <<= 1) {
                int t = __shfl_up_sync(0xffffffffu, wincl, o);
                if (lane >= o) wincl += t;
            }
            warp_sums[lane] = wincl - ws;
        }
        __syncthreads();
        int excl = incl - v + warp_sums[wid] + s_carry;
        if (i < NNODES) { g_rowptr[i] = excl; g_cur[i] = excl; }
        __syncthreads();
        if (tid == 1023) s_carry = excl + v;
        __syncthreads();
    }
    if (tid == 0) g_rowptr[NNODES] = NEDGES;
}

__global__ void fill_kernel(const int* __restrict__ ei, const float* __restrict__ ea) {
    int e = blockIdx.x * blockDim.x + threadIdx.x;
    if (e >= NEDGES) return;
    int d = ei[NEDGES + e];
    int pos = atomicAdd(&g_cur[d], 1);
    g_epack[pos] = make_int2(ei[e], __float_as_int(ea[e]));
}

__global__ void rezero_kernel() {
    int i = blockIdx.x * blockDim.x + threadIdx.x;
    if (i < NNODES) g_cur[i] = 0;
}

// ---------------------------------------------------------------------------
// FUSED layer 1: 7-feat gather + dense 7->128 (proven)
// ---------------------------------------------------------------------------
__global__ void gine7(const float* __restrict__ x, const float* __restrict__ We,
                      const float* __restrict__ be, const float* __restrict__ W,
                      const float* __restrict__ b) {
    __shared__ float sW[NFEAT * HID];
    __shared__ float sb[HID];
    __shared__ float sAgg[128 * NFEAT];
    int t = threadIdx.x;
    for (int i = t; i < NFEAT * HID; i += 128) sW[i] = W[i];
    sb[t] = b[t];

    int n0 = blockIdx.x * 128;
    int n  = n0 + t;

    if (n < NNODES) {
        float w[NFEAT], bb[NFEAT], acc[NFEAT];
#pragma unroll
        for (int f = 0; f < NFEAT; f++) { w[f] = __ldg(&We[f]); bb[f] = __ldg(&be[f]); }
#pragma unroll
        for (int f = 0; f < NFEAT; f++) acc[f] = x[n * NFEAT + f];
        int beg = g_rowptr[n], end = g_rowptr[n + 1];
        int e = beg;
        for (; e + 3 < end; e += 4) {
            int2 p0 = __ldg(&g_epack[e]),     p1 = __ldg(&g_epack[e + 1]);
            int2 p2 = __ldg(&g_epack[e + 2]), p3 = __ldg(&g_epack[e + 3]);
            float a0 = __int_as_float(p0.y), a1 = __int_as_float(p1.y);
            float a2 = __int_as_float(p2.y), a3 = __int_as_float(p3.y);
            float v0[NFEAT], v1[NFEAT], v2[NFEAT], v3[NFEAT];
#pragma unroll
            for (int f = 0; f < NFEAT; f++) v0[f] = __ldg(&x[p0.x * NFEAT + f]);
#pragma unroll
            for (int f = 0; f < NFEAT; f++) v1[f] = __ldg(&x[p1.x * NFEAT + f]);
#pragma unroll
            for (int f = 0; f < NFEAT; f++) v2[f] = __ldg(&x[p2.x * NFEAT + f]);
#pragma unroll
            for (int f = 0; f < NFEAT; f++) v3[f] = __ldg(&x[p3.x * NFEAT + f]);
#pragma unroll
            for (int f = 0; f < NFEAT; f++) {
                acc[f] += fmaxf(v0[f] + fmaf(a0, w[f], bb[f]), 0.f)
                        + fmaxf(v1[f] + fmaf(a1, w[f], bb[f]), 0.f)
                        + fmaxf(v2[f] + fmaf(a2, w[f], bb[f]), 0.f)
                        + fmaxf(v3[f] + fmaf(a3, w[f], bb[f]), 0.f);
            }
        }
        for (; e < end; e++) {
            int2 p = __ldg(&g_epack[e]);
            float a = __int_as_float(p.y);
#pragma unroll
            for (int f = 0; f < NFEAT; f++)
                acc[f] += fmaxf(__ldg(&x[p.x * NFEAT + f]) + fmaf(a, w[f], bb[f]), 0.f);
        }
#pragma unroll
        for (int f = 0; f < NFEAT; f++) sAgg[t * NFEAT + f] = acc[f];
    }
    __syncthreads();

    int cnt = NNODES - n0; if (cnt > 128) cnt = 128;
    for (int r = 0; r < cnt; r++) {
        float acc = sb[t];
#pragma unroll
        for (int k = 0; k < NFEAT; k++)
            acc = fmaf(sAgg[r * NFEAT + k], sW[k * HID + t], acc);
        float o = fmaxf(acc, 0.f);
        size_t idx = (size_t)(n0 + r) * HID + t;
        g_ha[idx]  = o;
        g_h16[idx] = __float2half_rn(o);
    }
}

// ---------------------------------------------------------------------------
// 128-feat gather (R7 best): warp per node, fp16 rows, 8-edge unroll
// ---------------------------------------------------------------------------
__device__ __forceinline__ void acc_edge(float4& acc, uint2 v, float a,
                                         const float4& w, const float4& bb) {
    __half2 h0 = *reinterpret_cast<__half2*>(&v.x);
    __half2 h1 = *reinterpret_cast<__half2*>(&v.y);
    float2 f0 = __half22float2(h0);
    float2 f1 = __half22float2(h1);
    acc.x += fmaxf(f0.x + fmaf(a, w.x, bb.x), 0.f);
    acc.y += fmaxf(f0.y + fmaf(a, w.y, bb.y), 0.f);
    acc.z += fmaxf(f1.x + fmaf(a, w.z, bb.z), 0.f);
    acc.w += fmaxf(f1.y + fmaf(a, w.w, bb.w), 0.f);
}

__global__ void gather128(const float* __restrict__ h32, const float* __restrict__ We,
                          const float* __restrict__ be, float* __restrict__ aggout) {
    int warp = (blockIdx.x * blockDim.x + threadIdx.x) >> 5;
    int lane = threadIdx.x & 31;
    if (warp >= NNODES) return;
    float4 w  = __ldg(&((const float4*)We)[lane]);
    float4 bb = __ldg(&((const float4*)be)[lane]);
    int beg = __ldg(&g_rowptr[warp]);
    int end = __ldg(&g_rowptr[warp + 1]);
    const uint2* h16 = (const uint2*)g_h16;
    float4 acc = ((const float4*)h32)[(size_t)warp * 32 + lane];

    int e = beg;
    for (; e + 7 < end; e += 8) {
        int2 p[8];
#pragma unroll
        for (int i = 0; i < 8; i++) p[i] = __ldg(&g_epack[e + i]);
        uint2 v[8];
#pragma unroll
        for (int i = 0; i < 8; i++) v[i] = __ldg(&h16[(size_t)p[i].x * 32 + lane]);
#pragma unroll
        for (int i = 0; i < 8; i++)
            acc_edge(acc, v[i], __int_as_float(p[i].y), w, bb);
    }
    for (; e + 1 < end; e += 2) {
        int2 p0 = __ldg(&g_epack[e]), p1 = __ldg(&g_epack[e + 1]);
        uint2 v0 = __ldg(&h16[(size_t)p0.x * 32 + lane]);
        uint2 v1 = __ldg(&h16[(size_t)p1.x * 32 + lane]);
        acc_edge(acc, v0, __int_as_float(p0.y), w, bb);
        acc_edge(acc, v1, __int_as_float(p1.y), w, bb);
    }
    if (e < end) {
        int2 p0 = __ldg(&g_epack[e]);
        uint2 v0 = __ldg(&h16[(size_t)p0.x * 32 + lane]);
        acc_edge(acc, v0, __int_as_float(p0.y), w, bb);
    }
    ((float4*)aggout)[(size_t)warp * 32 + lane] = acc;
}

// ---------------------------------------------------------------------------
// fp16 mma.sync dense with W-error compensation:
// out = relu( A @ (Whi + Wlo) + b ), Whi = fp16(W), Wlo = fp16(W - Whi).
// A converted to fp16 (per-node error pools away in the graph mean).
// Block: 256 thr / 8 warps; tile 128 nodes x 128 cols; warp tile 64x32.
// mma.sync.aligned.m16n8k16.row.col.f32.f16.f16.f32
// smem (halfs, stride 136): A[128][136], Bhi[128][136](j-major), Blo same.
// ---------------------------------------------------------------------------
#define SAH 136
#define SBH 136
#define SMEM_HM ((128 * SAH + 2 * 128 * SBH) * 2)   // bytes = 104448

__device__ __forceinline__ void mma16(float4& d, const uint32_t a[4], const uint32_t b[2]) {
    asm volatile(
        "mma.sync.aligned.m16n8k16.row.col.f32.f16.f16.f32 "
        "{%0,%1,%2,%3}, {%4,%5,%6,%7}, {%8,%9}, {%0,%1,%2,%3};\n"
        : "+f"(d.x), "+f"(d.y), "+f"(d.z), "+f"(d.w)
        : "r"(a[0]), "r"(a[1]), "r"(a[2]), "r"(a[3]), "r"(b[0]), "r"(b[1]));
}

__global__ void __launch_bounds__(256, 2)
dense128_hmma(const float* __restrict__ A, const float* __restrict__ W,
              const float* __restrict__ b, float* __restrict__ out, int write16) {
    extern __shared__ __half sm[];
    __half* sA  = sm;                    // [r][k] stride SAH
    __half* sBh = sm + 128 * SAH;        // [j][k] stride SBH
    __half* sBl = sBh + 128 * SBH;

    int t = threadIdx.x;
    int m0 = blockIdx.x * 128;

    // Stage W -> Bhi/Blo fp16, [j][k]
    for (int i = t; i < HID * HID; i += 256) {
        int k = i >> 7, j = i & 127;
        float v = __ldg(&W[k * HID + j]);
        __half hi = __float2half_rn(v);
        __half lo = __float2half_rn(v - __half2float(hi));
        sBh[j * SBH + k] = hi;
        sBl[j * SBH + k] = lo;
    }
    // Stage A tile -> fp16, [r][k]
    for (int i = t; i < 128 * 32; i += 256) {
        int r = i >> 5, c4 = (i & 31) * 4;
        int n = m0 + r;
        float4 v = make_float4(0.f, 0.f, 0.f, 0.f);
        if (n < NNODES) v = __ldg(&((const float4*)A)[(size_t)n * 32 + (c4 >> 2)]);
        __half2 h0 = __floats2half2_rn(v.x, v.y);
        __half2 h1 = __floats2half2_rn(v.z, v.w);
        *(uint2*)(sA + r * SAH + c4) =
            make_uint2(*reinterpret_cast<uint32_t*>(&h0), *reinterpret_cast<uint32_t*>(&h1));
    }
    __syncthreads();

    int lane = t & 31, wid = t >> 5;
    int gid = lane >> 2, tig = lane & 3;
    int rowbase = (wid & 1) * 64;      // warp_m in {0,1}
    int colbase = (wid >> 1) * 32;     // warp_n in {0..3}

    float4 acc[4][4];
#pragma unroll
    for (int i = 0; i < 4; i++)
#pragma unroll
        for (int j = 0; j < 4; j++) acc[i][j] = make_float4(0.f, 0.f, 0.f, 0.f);

#pragma unroll 2
    for (int ks = 0; ks < 8; ks++) {
        int k0 = ks * 16;
        uint32_t a[4][4];
#pragma unroll
        for (int mf = 0; mf < 4; mf++) {
            const __half* pa = sA + (rowbase + mf * 16 + gid) * SAH + k0 + 2 * tig;
            a[mf][0] = *(const uint32_t*)(pa);
            a[mf][1] = *(const uint32_t*)(pa + 8 * SAH);
            a[mf][2] = *(const uint32_t*)(pa + 8);
            a[mf][3] = *(const uint32_t*)(pa + 8 * SAH + 8);
        }
        uint32_t bh[4][2], bl[4][2];
#pragma unroll
        for (int nf = 0; nf < 4; nf++) {
            int j = colbase + nf * 8 + gid;
            const __half* pbh = sBh + j * SBH + k0 + 2 * tig;
            const __half* pbl = sBl + j * SBH + k0 + 2 * tig;
            bh[nf][0] = *(const uint32_t*)(pbh);
            bh[nf][1] = *(const uint32_t*)(pbh + 8);
            bl[nf][0] = *(const uint32_t*)(pbl);
            bl[nf][1] = *(const uint32_t*)(pbl + 8);
        }
#pragma unroll
        for (int mf = 0; mf < 4; mf++)
#pragma unroll
            for (int nf = 0; nf < 4; nf++) {
                mma16(acc[mf][nf], a[mf], bh[nf]);
                mma16(acc[mf][nf], a[mf], bl[nf]);
            }
    }

    // Epilogue: bias + relu, fp32 out (+ optional fp16 mirror)
#pragma unroll
    for (int nf = 0; nf < 4; nf++) {
        int col = colbase + nf * 8 + tig * 2;
        float bx = __ldg(&b[col]), by = __ldg(&b[col + 1]);
#pragma unroll
        for (int mf = 0; mf < 4; mf++) {
            int r0 = m0 + rowbase + mf * 16 + gid;
            int r1 = r0 + 8;
            float4 v = acc[mf][nf];
            if (r0 < NNODES) {
                float2 o = make_float2(fmaxf(v.x + bx, 0.f), fmaxf(v.y + by, 0.f));
                *(float2*)(out + (size_t)r0 * HID + col) = o;
                if (write16) {
                    __half2 h = __floats2half2_rn(o.x, o.y);
                    *(uint32_t*)((__half*)g_h16 + (size_t)r0 * HID + col) =
                        *reinterpret_cast<uint32_t*>(&h);
                }
            }
            if (r1 < NNODES) {
                float2 o = make_float2(fmaxf(v.z + bx, 0.f), fmaxf(v.w + by, 0.f));
                *(float2*)(out + (size_t)r1 * HID + col) = o;
                if (write16) {
                    __half2 h = __floats2half2_rn(o.x, o.y);
                    *(uint32_t*)((__half*)g_h16 + (size_t)r1 * HID + col) =
                        *reinterpret_cast<uint32_t*>(&h);
                }
            }
        }
    }
}

// ---------------------------------------------------------------------------
// Pooling + head
// ---------------------------------------------------------------------------
__global__ void pool_init() {
    int t = blockIdx.x * blockDim.x + threadIdx.x;
    if (t < NGRAPH * HID) g_pool[t] = 0.f;
    if (t < NGRAPH) g_cnt[t] = 0.f;
}

__global__ void pool_kernel(const float* __restrict__ h, const int* __restrict__ batch) {
    int f = threadIdx.x;
    int n0 = blockIdx.x * 256;
    int n1 = n0 + 256; if (n1 > NNODES) n1 = NNODES;
    if (n0 >= NNODES) return;
    float acc = 0.f, c = 0.f;
    int curg = batch[n0];
    for (int n = n0; n < n1; n++) {
        int g = batch[n];
        if (g != curg) {
            atomicAdd(&g_pool[curg * HID + f], acc);
            if (f == 0) atomicAdd(&g_cnt[curg], c);
            acc = 0.f; c = 0.f; curg = g;
        }
        acc += h[(size_t)n * HID + f];
        c += 1.f;
    }
    atomicAdd(&g_pool[curg * HID + f], acc);
    if (f == 0) atomicAdd(&g_cnt[curg], c);
}

__global__ void final_kernel(const float* __restrict__ Wlin, const float* __restrict__ blin,
                             float* __restrict__ out) {
    int t = threadIdx.x;
    if (t >= NGRAPH * NCLASS) return;
    int g = t / NCLASS, c = t % NCLASS;
    float cnt = fmaxf(g_cnt[g], 1.f);
    float acc = blin[c];
#pragma unroll 8
    for (int f = 0; f < HID; f++)
        acc = fmaf(g_pool[g * HID + f] / cnt, Wlin[f * NCLASS + c], acc);
    out[t] = acc;
}

// ---------------------------------------------------------------------------
// Launch
// ---------------------------------------------------------------------------
extern "C" void kernel_launch(void* const* d_in, const int* in_sizes, int n_in,
                              void* d_out, int out_size) {
    const float* x     = (const float*)d_in[0];
    const int*   ei    = (const int*)d_in[1];
    const float* ea    = (const float*)d_in[2];
    const int*   batch = (const int*)d_in[3];
    const float* We1 = (const float*)d_in[4],  *be1 = (const float*)d_in[5];
    const float* W1  = (const float*)d_in[6],  *b1  = (const float*)d_in[7];
    const float* We2 = (const float*)d_in[8],  *be2 = (const float*)d_in[9];
    const float* W2  = (const float*)d_in[10], *b2  = (const float*)d_in[11];
    const float* We3 = (const float*)d_in[12], *be3 = (const float*)d_in[13];
    const float* W3  = (const float*)d_in[14], *b3  = (const float*)d_in[15];
    const float* Wlin = (const float*)d_in[16], *blin = (const float*)d_in[17];
    float* out = (float*)d_out;

    void *aggp, *hap, *hbp;
    cudaGetSymbolAddress(&aggp, g_agg);
    cudaGetSymbolAddress(&hap,  g_ha);
    cudaGetSymbolAddress(&hbp,  g_hb);
    float* agg = (float*)aggp;
    float* ha  = (float*)hap;
    float* hb  = (float*)hbp;

    cudaFuncSetAttribute(dense128_hmma, cudaFuncAttributeMaxDynamicSharedMemorySize, SMEM_HM);

    const int EBLK = (NEDGES + 255) / 256;
    const int G128_BLOCKS = (NNODES * 32 + 255) / 256;   // warp per node
    const int DT_BLOCKS   = (NNODES + 127) / 128;

    // CSR build (g_cur enters zeroed; rezero at end restores invariant)
    hist_kernel<<<EBLK, 256>>>(ei);
    scan_kernel<<<1, 1024>>>();
    fill_kernel<<<EBLK, 256>>>(ei, ea);

    // Layer 1 fused
    gine7<<<(NNODES + 127) / 128, 128>>>(x, We1, be1, W1, b1);           // -> ha + h16

    // Layer 2
    gather128<<<G128_BLOCKS, 256>>>(ha, We2, be2, agg);                  // reads h16(h1)
    dense128_hmma<<<DT_BLOCKS, 256, SMEM_HM>>>(agg, W2, b2, hb, 1);      // -> hb + h16

    // Layer 3
    gather128<<<G128_BLOCKS, 256>>>(hb, We3, be3, agg);                  // reads h16(h2)
    dense128_hmma<<<DT_BLOCKS, 256, SMEM_HM>>>(agg, W3, b3, ha, 0);      // -> ha

    // Mean pool + linear head
    pool_init<<<8, 128>>>();
    pool_kernel<<<(NNODES + 255) / 256, 128>>>(ha, batch);
    final_kernel<<<1, 64>>>(Wlin, blin, out);

    rezero_kernel<<<(NNODES + 255) / 256, 256>>>();
}